// round 16
// baseline (speedup 1.0000x reference)
#include <cuda_runtime.h>
#include <cuda_fp16.h>
#include <math.h>
#include <stdint.h>

#define BB   2
#define SEQ  4096
#define CDIM 768
#define NH   8
#define HD   96
#define QSC  (0.10206207261596575f * 1.4426950408889634f)   // SCALE*log2(e)
#define M_TOT (BB*SEQ)

// Scratch (allocation-free rule: __device__ globals)
__device__ __half g_Xh [M_TOT*CDIM];     // X in fp16
__device__ __half g_Wqh[3*CDIM*CDIM];    // Wqkv in fp16
__device__ __half g_PWh[CDIM*CDIM];      // Wproj hi fp16
__device__ __half g_Qh[BB*NH*SEQ*HD];    // pre-scaled by QSC, fp16
__device__ __half g_Kh[BB*NH*SEQ*HD];    // fp16
__device__ __half g_Vth[BB*NH*HD*SEQ];   // fp16, TRANSPOSED per head: [b,h,d,n]
__device__ __half g_POh[M_TOT*CDIM];     // attention out hi fp16
__device__ __half g_POl[M_TOT*CDIM];     // attention out lo fp16

// ===========================================================================
// helpers
// ===========================================================================
__device__ __forceinline__ float ex2f(float x) {
    float y;
    asm("ex2.approx.ftz.f32 %0, %1;" : "=f"(y) : "f"(x));
    return y;
}
__device__ __forceinline__ uint32_t packh2(float lo, float hi) {  // {h0=lo, h1=hi}
    uint32_t d;
    asm("cvt.rn.f16x2.f32 %0, %1, %2;" : "=r"(d) : "f"(hi), "f"(lo));
    return d;
}
__device__ __forceinline__ void mma16(float* c,
                                      uint32_t a0, uint32_t a1, uint32_t a2, uint32_t a3,
                                      uint32_t b0, uint32_t b1) {
    asm volatile(
        "mma.sync.aligned.m16n8k16.row.col.f32.f16.f16.f32 "
        "{%0,%1,%2,%3}, {%4,%5,%6,%7}, {%8,%9}, {%0,%1,%2,%3};"
        : "+f"(c[0]), "+f"(c[1]), "+f"(c[2]), "+f"(c[3])
        : "r"(a0), "r"(a1), "r"(a2), "r"(a3), "r"(b0), "r"(b1));
}
__device__ __forceinline__ uint32_t smem_u32(const void* p) {
    uint32_t a;
    asm("{ .reg .u64 t; cvta.to.shared.u64 t, %1; cvt.u32.u64 %0, t; }" : "=r"(a) : "l"(p));
    return a;
}
__device__ __forceinline__ void cpasync16(uint32_t dst, const void* src) {
    asm volatile("cp.async.cg.shared.global [%0], [%1], 16;" :: "r"(dst), "l"(src));
}
__device__ __forceinline__ void cp_commit() {
    asm volatile("cp.async.commit_group;" ::: "memory");
}
__device__ __forceinline__ void cp_wait0() {
    asm volatile("cp.async.wait_group 0;" ::: "memory");
}

// ===========================================================================
// Kernel 0: one-time fp32 -> fp16 conversion of X, Wqkv, Wproj(hi).
// ===========================================================================
#define NX4  (M_TOT*CDIM/4)
#define NWQ4 (3*CDIM*CDIM/4)
#define NWP4 (CDIM*CDIM/4)
#define CONV_BLOCKS ((NX4 + NWQ4 + NWP4 + 255)/256)

__global__ __launch_bounds__(256) void conv_in(const float* __restrict__ X,
                                               const float* __restrict__ Wq,
                                               const float* __restrict__ Wp) {
    int idx = blockIdx.x * 256 + threadIdx.x;
    if (idx < NX4) {
        float4 v = ((const float4*)X)[idx];
        ((__half2*)g_Xh)[idx*2    ] = __floats2half2_rn(v.x, v.y);
        ((__half2*)g_Xh)[idx*2 + 1] = __floats2half2_rn(v.z, v.w);
    } else if (idx < NX4 + NWQ4) {
        int j = idx - NX4;
        float4 v = ((const float4*)Wq)[j];
        ((__half2*)g_Wqh)[j*2    ] = __floats2half2_rn(v.x, v.y);
        ((__half2*)g_Wqh)[j*2 + 1] = __floats2half2_rn(v.z, v.w);
    } else if (idx < NX4 + NWQ4 + NWP4) {
        int j = idx - NX4 - NWQ4;
        float4 v = ((const float4*)Wp)[j];
        ((__half2*)g_PWh)[j*2    ] = __floats2half2_rn(v.x, v.y);
        ((__half2*)g_PWh)[j*2 + 1] = __floats2half2_rn(v.z, v.w);
    }
}

// ===========================================================================
// Kernel 1: QKV GEMM, pure-fp16 cp.async 2-stage (unchanged from R14).
// ===========================================================================
#define QP   72
#define QSTG (128*QP*2)
#define QKV_SMEM (4*QSTG)            // 73728
#define PT 130

__device__ __forceinline__ void qkv_prefetch(uint32_t sb, int st,
                                             const __half* Ab, const __half* Bb,
                                             int itk, int tid) {
#pragma unroll
    for (int i = 0; i < 4; i++) {
        int f = tid + i * 256;
        int row = f >> 3, c = f & 7;
        cpasync16(sb + st*QSTG + row*144 + c*16,
                  Ab + (size_t)row*CDIM + itk*64 + c*8);
        cpasync16(sb + 2*QSTG + st*QSTG + row*144 + c*16,
                  Bb + (size_t)row*CDIM + itk*64 + c*8);
    }
}

__global__ __launch_bounds__(256) void qkv_tc() {
    extern __shared__ char dsm[];
    const uint32_t sb = smem_u32(dsm);
    const int tid  = threadIdx.x;
    const int wid  = tid >> 5;
    const int lane = tid & 31;
    const int g    = lane >> 2;
    const int tig  = lane & 3;
    const int mw = wid >> 1, nw = wid & 1;
    const int m0 = blockIdx.y * 128;
    const int o0 = blockIdx.x * 128;
    const __half* Ab = g_Xh + (size_t)m0 * CDIM;
    const __half* Bb = g_Wqh + (size_t)o0 * CDIM;

    float acc[2][8][4];
#pragma unroll
    for (int mi = 0; mi < 2; mi++)
#pragma unroll
        for (int v = 0; v < 8; v++)
#pragma unroll
            for (int j = 0; j < 4; j++) acc[mi][v][j] = 0.f;

    qkv_prefetch(sb, 0, Ab, Bb, 0, tid);
    cp_commit();

    for (int it = 0; it < 12; it++) {
        cp_wait0();
        __syncthreads();
        if (it + 1 < 12) {
            qkv_prefetch(sb, (it + 1) & 1, Ab, Bb, it + 1, tid);
            cp_commit();
        }
        const __half* As = (const __half*)(dsm + (it & 1) * QSTG);
        const __half* Bs = (const __half*)(dsm + 2*QSTG + (it & 1) * QSTG);
#pragma unroll
        for (int ks = 0; ks < 4; ks++) {
            const int kc = ks*16 + 2*tig;
            uint32_t a[2][4];
#pragma unroll
            for (int mi = 0; mi < 2; mi++) {
                int row = mw*32 + mi*16 + g;
                a[mi][0] = *(const uint32_t*)&As[row      * QP + kc];
                a[mi][1] = *(const uint32_t*)&As[(row + 8)* QP + kc];
                a[mi][2] = *(const uint32_t*)&As[row      * QP + kc + 8];
                a[mi][3] = *(const uint32_t*)&As[(row + 8)* QP + kc + 8];
            }
#pragma unroll
            for (int v = 0; v < 8; v++) {
                int col = nw*64 + v*8 + g;
                uint32_t b0 = *(const uint32_t*)&Bs[col * QP + kc];
                uint32_t b1 = *(const uint32_t*)&Bs[col * QP + kc + 8];
                mma16(acc[0][v], a[0][0], a[0][1], a[0][2], a[0][3], b0, b1);
                mma16(acc[1][v], a[1][0], a[1][1], a[1][2], a[1][3], b0, b1);
            }
        }
    }
    __syncthreads();

    const int which = o0 / CDIM;
    const int oc0 = o0 - which * CDIM;
    const int bb = m0 >> 12;
    const int n0 = m0 & (SEQ - 1);

    if (which < 2) {
        __half* dstg = (which == 0) ? g_Qh : g_Kh;
        const float mul = (which == 0) ? QSC : 1.0f;
#pragma unroll
        for (int mi = 0; mi < 2; mi++) {
#pragma unroll
            for (int rr = 0; rr < 2; rr++) {
                int n = n0 + mw*32 + mi*16 + g + rr*8;
#pragma unroll
                for (int v = 0; v < 8; v++) {
                    int c = oc0 + nw*64 + v*8 + 2*tig;
                    int h = c / HD, d = c - h * HD;
                    __half2 hv = __floats2half2_rn(acc[mi][v][rr*2]     * mul,
                                                   acc[mi][v][rr*2 + 1] * mul);
                    *(__half2*)&dstg[((size_t)(bb*NH + h) * SEQ + n) * HD + d] = hv;
                }
            }
        }
    } else {
        __half* T = (__half*)dsm;
#pragma unroll
        for (int mi = 0; mi < 2; mi++) {
#pragma unroll
            for (int rr = 0; rr < 2; rr++) {
                int nl = mw*32 + mi*16 + g + rr*8;
#pragma unroll
                for (int v = 0; v < 8; v++) {
                    int cl = nw*64 + v*8 + 2*tig;
                    *(__half2*)&T[nl * PT + cl] =
                        __floats2half2_rn(acc[mi][v][rr*2], acc[mi][v][rr*2 + 1]);
                }
            }
        }
        __syncthreads();
        const size_t vrow0 = (size_t)(bb * NH * HD + oc0);
#pragma unroll
        for (int i = 0; i < 8; i++) {
            int f = tid + i * 256;
            int row = f >> 4;
            int ch  = f & 15;
            __half tmp[8];
#pragma unroll
            for (int j = 0; j < 8; j++) tmp[j] = T[(ch*8 + j) * PT + row];
            *(uint4*)&g_Vth[(vrow0 + row) * SEQ + n0 + ch*8] = *(uint4*)tmp;
        }
    }
}

// ===========================================================================
// Kernel 2: flash attention, fp16 m16n8k16, q-tile 64, 2 CTAs/SM.
// 8 warps 4Mx2N: warp owns 16 q-rows x 64 keys. K single-stage (2 syncs/kt),
// V double-stage. Co-resident CTA fills sync/softmax bubbles.
// smem: Q 13312 | K 26624 | V 2x26112 = 92160 B.
// ===========================================================================
#define QT   64
#define PQH 104
#define PKH 104
#define PVH 136
#define Q_SZ   (QT*PQH*2)              // 13312
#define K_SZ   (128*PKH*2)             // 26624
#define VSTG2  (96*PVH*2)              // 26112
#define SMK_OFF Q_SZ                   // 13312
#define SMV_OFF (SMK_OFF + K_SZ)       // 39936
#define ATTN_SMEM (SMV_OFF + 2*VSTG2)  // 92160

__device__ __forceinline__ void cp_tile_q(uint32_t dst, const __half* src, int tid) {
#pragma unroll
    for (int i = 0; i < 3; i++) {
        int cf  = tid + i * 256;        // 0..767
        int row = cf / 12;
        int c   = cf - row * 12;
        cpasync16(dst + row * (PQH*2) + c * 16, src + (size_t)row * HD + c * 8);
    }
}
__device__ __forceinline__ void cp_tile_k(uint32_t dst, const __half* src, int tid) {
#pragma unroll
    for (int i = 0; i < 6; i++) {
        int cf  = tid + i * 256;
        int row = cf / 12;
        int c   = cf - row * 12;
        cpasync16(dst + row * (PKH*2) + c * 16, src + (size_t)row * HD + c * 8);
    }
}
__device__ __forceinline__ void cp_tile_v(uint32_t dst, const __half* src, int tid) {
#pragma unroll
    for (int i = 0; i < 6; i++) {
        int cf  = tid + i * 256;
        int row = cf >> 4;
        int c   = cf & 15;
        cpasync16(dst + row * (PVH*2) + c * 16, src + (size_t)row * SEQ + c * 8);
    }
}

__global__ __launch_bounds__(256, 2) void attn_mma() {
    extern __shared__ char smc[];
    const uint32_t sb = smem_u32(smc);
    const __half* Qh = (const __half*)smc;
    const __half* Ksh = (const __half*)(smc + SMK_OFF);
    __shared__ float l_red[2][QT];

    const int tid  = threadIdx.x;
    const int wid  = tid >> 5;
    const int lane = tid & 31;
    const int g    = lane >> 2;
    const int tig  = lane & 3;
    const int mw = wid >> 1, nw = wid & 1;
    const int q0 = blockIdx.x * QT;
    const int bh = blockIdx.y;
    const int bbv = bh >> 3, hh = bh & 7;
    const size_t base  = (size_t)bh * SEQ * HD;
    const size_t vbase = (size_t)bh * HD * SEQ;

    cp_tile_q(sb, &g_Qh[base + (size_t)q0 * HD], tid);
    cp_tile_k(sb + SMK_OFF, &g_Kh[base], tid);
    cp_tile_v(sb + SMV_OFF, &g_Vth[vbase], tid);
    cp_commit();

    float oacc[12][4];
#pragma unroll
    for (int v = 0; v < 12; v++)
#pragma unroll
        for (int j = 0; j < 4; j++) oacc[v][j] = 0.f;
    float lsum[2] = {0.f, 0.f};

    const int arow = mw*16 + g;

    for (int kt = 0; kt < SEQ / 128; kt++) {
        cp_wait0();
        __syncthreads();               // K(kt), V(kt) ready; prev PV done
        if (kt + 1 < SEQ / 128) {
            cp_tile_v(sb + SMV_OFF + ((kt + 1) & 1) * VSTG2,
                      &g_Vth[vbase + (size_t)(kt + 1) * 128], tid);
            cp_commit();
        }
        const __half* Vsh = (const __half*)(smc + SMV_OFF + (kt & 1) * VSTG2);

        // ---- S = Q K^T : warp rows arow/arow+8, keys nw*64.. ----
        float sacc[8][4];
#pragma unroll
        for (int v = 0; v < 8; v++)
#pragma unroll
            for (int j = 0; j < 4; j++) sacc[v][j] = 0.f;

#pragma unroll
        for (int t = 0; t < 6; t++) {
            const int kc = t*16 + 2*tig;
            uint32_t a0 = *(const uint32_t*)&Qh[arow      * PQH + kc];
            uint32_t a1 = *(const uint32_t*)&Qh[(arow + 8)* PQH + kc];
            uint32_t a2 = *(const uint32_t*)&Qh[arow      * PQH + kc + 8];
            uint32_t a3 = *(const uint32_t*)&Qh[(arow + 8)* PQH + kc + 8];
#pragma unroll
            for (int v = 0; v < 8; v++) {
                int col = nw*64 + v*8 + g;
                uint32_t b0 = *(const uint32_t*)&Ksh[col * PKH + kc];
                uint32_t b1 = *(const uint32_t*)&Ksh[col * PKH + kc + 8];
                mma16(sacc[v], a0, a1, a2, a3, b0, b1);
            }
        }
        __syncthreads();               // K consumed by all warps
        if (kt + 1 < SEQ / 128) {
            cp_tile_k(sb + SMK_OFF, &g_Kh[base + (size_t)(kt + 1) * 128 * HD], tid);
            cp_commit();
        }

        // ---- fused softmax + PV ----
#pragma unroll
        for (int ks = 0; ks < 4; ks++) {
            float* u0 = sacc[2*ks];
            float* u1 = sacc[2*ks + 1];
            float e0 = ex2f(u0[0]), e1 = ex2f(u0[1]);
            float e2 = ex2f(u0[2]), e3 = ex2f(u0[3]);
            float f0 = ex2f(u1[0]), f1 = ex2f(u1[1]);
            float f2 = ex2f(u1[2]), f3 = ex2f(u1[3]);
            lsum[0] += (e0 + e1) + (f0 + f1);
            lsum[1] += (e2 + e3) + (f2 + f3);
            uint32_t pa0 = packh2(e0, e1);
            uint32_t pa1 = packh2(e2, e3);
            uint32_t pa2 = packh2(f0, f1);
            uint32_t pa3 = packh2(f2, f3);
            const int key0 = nw*64 + ks*16 + 2*tig;
#pragma unroll
            for (int v = 0; v < 12; v++) {
                uint32_t b0 = *(const uint32_t*)&Vsh[(v*8 + g) * PVH + key0];
                uint32_t b1 = *(const uint32_t*)&Vsh[(v*8 + g) * PVH + key0 + 8];
                mma16(oacc[v], pa0, pa1, pa2, pa3, b0, b1);
            }
        }
    }

    // ---- epilogue: cross-nw reduction of l and O ----
    __syncthreads();
#pragma unroll
    for (int h = 0; h < 2; h++) {
        float l = lsum[h];
        l += __shfl_xor_sync(0xffffffffu, l, 1);
        l += __shfl_xor_sync(0xffffffffu, l, 2);
        lsum[h] = l;
    }
    if (tig == 0) {
#pragma unroll
        for (int h = 0; h < 2; h++)
            l_red[nw][arow + h*8] = lsum[h];
    }
    float* red = (float*)(smc + SMK_OFF);     // K area free now; pitch 100 fp32
    if (nw == 1) {
#pragma unroll
        for (int h = 0; h < 2; h++) {
            int row = arow + h*8;
#pragma unroll
            for (int v = 0; v < 12; v++)
                *(float2*)&red[row * 100 + v*8 + 2*tig] =
                    make_float2(oacc[v][2*h], oacc[v][2*h + 1]);
        }
    }
    __syncthreads();
    if (nw == 0) {
#pragma unroll
        for (int h = 0; h < 2; h++) {
            int row = arow + h*8;
            float inv = 1.f / (l_red[0][row] + l_red[1][row]);
            int n = q0 + row;
            size_t ob = ((size_t)bbv * SEQ + n) * CDIM + hh * HD;
#pragma unroll
            for (int v = 0; v < 12; v++) {
                float2 p = *(float2*)&red[row * 100 + v*8 + 2*tig];
                float v0 = (oacc[v][2*h]     + p.x) * inv;
                float v1 = (oacc[v][2*h + 1] + p.y) * inv;
                __half h0 = __float2half_rn(v0);
                __half h1 = __float2half_rn(v1);
                __half l0 = __float2half_rn(v0 - __half2float(h0));
                __half l1 = __float2half_rn(v1 - __half2float(h1));
                size_t off = ob + v*8 + 2*tig;
                *(__half2*)&g_POh[off] = __halves2half2(h0, h1);
                *(__half2*)&g_POl[off] = __halves2half2(l0, l1);
            }
        }
    }
}

// ===========================================================================
// Kernel 3: output projection, 2-term compensated fp16 (unchanged from R14).
// ===========================================================================
#define PP   40
#define PSTG (128*PP*2)
#define PROJ_SMEM (6*PSTG)             // 61440

__device__ __forceinline__ void proj_prefetch(uint32_t sb, int st,
                                              const __half* AhG, const __half* AlG,
                                              const __half* BhG, int itk, int tid) {
#pragma unroll
    for (int i = 0; i < 2; i++) {
        int f = tid + i * 256;
        int row = f >> 2, c = f & 3;
        cpasync16(sb + st*PSTG + row*80 + c*16,
                  AhG + (size_t)row*CDIM + itk*32 + c*8);
        cpasync16(sb + 2*PSTG + st*PSTG + row*80 + c*16,
                  AlG + (size_t)row*CDIM + itk*32 + c*8);
        cpasync16(sb + 4*PSTG + st*PSTG + row*80 + c*16,
                  BhG + (size_t)row*CDIM + itk*32 + c*8);
    }
}

__global__ __launch_bounds__(256) void proj_tc(float* __restrict__ out) {
    extern __shared__ char dsm[];
    const uint32_t sb = smem_u32(dsm);
    const int tid  = threadIdx.x;
    const int wid  = tid >> 5;
    const int lane = tid & 31;
    const int g    = lane >> 2;
    const int tig  = lane & 3;
    const int mw = wid >> 1, nw = wid & 1;
    const int m0 = blockIdx.y * 128;
    const int o0 = blockIdx.x * 128;
    const __half* AhG = g_POh + (size_t)m0 * CDIM;
    const __half* AlG = g_POl + (size_t)m0 * CDIM;
    const __half* BhG = g_PWh + (size_t)o0 * CDIM;

    float acc[2][8][4];
#pragma unroll
    for (int mi = 0; mi < 2; mi++)
#pragma unroll
        for (int v = 0; v < 8; v++)
#pragma unroll
            for (int j = 0; j < 4; j++) acc[mi][v][j] = 0.f;

    proj_prefetch(sb, 0, AhG, AlG, BhG, 0, tid);
    cp_commit();

    for (int it = 0; it < 24; it++) {
        cp_wait0();
        __syncthreads();
        if (it + 1 < 24) {
            proj_prefetch(sb, (it + 1) & 1, AhG, AlG, BhG, it + 1, tid);
            cp_commit();
        }
        const __half* Ah = (const __half*)(dsm + (it & 1) * PSTG);
        const __half* Al = (const __half*)(dsm + 2*PSTG + (it & 1) * PSTG);
        const __half* Bh = (const __half*)(dsm + 4*PSTG + (it & 1) * PSTG);
#pragma unroll
        for (int ks = 0; ks < 2; ks++) {
            const int kc = ks*16 + 2*tig;
            uint32_t ah[2][4], al[2][4];
#pragma unroll
            for (int mi = 0; mi < 2; mi++) {
                int row = mw*32 + mi*16 + g;
                ah[mi][0] = *(const uint32_t*)&Ah[row      * PP + kc];
                ah[mi][1] = *(const uint32_t*)&Ah[(row + 8)* PP + kc];
                ah[mi][2] = *(const uint32_t*)&Ah[row      * PP + kc + 8];
                ah[mi][3] = *(const uint32_t*)&Ah[(row + 8)* PP + kc + 8];
                al[mi][0] = *(const uint32_t*)&Al[row      * PP + kc];
                al[mi][1] = *(const uint32_t*)&Al[(row + 8)* PP + kc];
                al[mi][2] = *(const uint32_t*)&Al[row      * PP + kc + 8];
                al[mi][3] = *(const uint32_t*)&Al[(row + 8)* PP + kc + 8];
            }
#pragma unroll
            for (int v = 0; v < 8; v++) {
                int col = nw*64 + v*8 + g;
                uint32_t b0 = *(const uint32_t*)&Bh[col * PP + kc];
                uint32_t b1 = *(const uint32_t*)&Bh[col * PP + kc + 8];
#pragma unroll
                for (int mi = 0; mi < 2; mi++) {
                    mma16(acc[mi][v], al[mi][0], al[mi][1], al[mi][2], al[mi][3], b0, b1);
                    mma16(acc[mi][v], ah[mi][0], ah[mi][1], ah[mi][2], ah[mi][3], b0, b1);
                }
            }
        }
    }

#pragma unroll
    for (int mi = 0; mi < 2; mi++) {
#pragma unroll
        for (int rr = 0; rr < 2; rr++) {
            int m = m0 + mw*32 + mi*16 + g + rr*8;
#pragma unroll
            for (int v = 0; v < 8; v++) {
                int o = o0 + nw*64 + v*8 + 2*tig;
                *(float2*)&out[(size_t)m * CDIM + o] =
                    make_float2(acc[mi][v][rr*2], acc[mi][v][rr*2 + 1]);
            }
        }
    }
}

// ===========================================================================
extern "C" void kernel_launch(void* const* d_in, const int* in_sizes, int n_in,
                              void* d_out, int out_size) {
    const float *x = nullptr, *w_qkv = nullptr, *w_proj = nullptr;
    for (int i = 0; i < n_in; i++) {
        if (in_sizes[i] == BB * SEQ * CDIM)       x      = (const float*)d_in[i];
        else if (in_sizes[i] == 3 * CDIM * CDIM)  w_qkv  = (const float*)d_in[i];
        else if (in_sizes[i] == CDIM * CDIM)      w_proj = (const float*)d_in[i];
    }
    float* out = (float*)d_out;

    conv_in<<<CONV_BLOCKS, 256>>>(x, w_qkv, w_proj);

    cudaFuncSetAttribute(qkv_tc, cudaFuncAttributeMaxDynamicSharedMemorySize, QKV_SMEM);
    qkv_tc<<<dim3(3*CDIM/128, M_TOT/128), 256, QKV_SMEM>>>();

    cudaFuncSetAttribute(attn_mma, cudaFuncAttributeMaxDynamicSharedMemorySize, ATTN_SMEM);
    attn_mma<<<dim3(SEQ/QT, BB*NH), 256, ATTN_SMEM>>>();

    cudaFuncSetAttribute(proj_tc, cudaFuncAttributeMaxDynamicSharedMemorySize, PROJ_SMEM);
    proj_tc<<<dim3(CDIM/128, M_TOT/128), 256, PROJ_SMEM>>>(out);
}

// round 17
// speedup vs baseline: 1.0683x; 1.0683x over previous
#include <cuda_runtime.h>
#include <cuda_fp16.h>
#include <math.h>
#include <stdint.h>

#define BB   2
#define SEQ  4096
#define CDIM 768
#define NH   8
#define HD   96
#define QSC  (0.10206207261596575f * 1.4426950408889634f)   // SCALE*log2(e)
#define M_TOT (BB*SEQ)

// Scratch (allocation-free rule: __device__ globals)
__device__ __half g_Xh [M_TOT*CDIM];     // X in fp16
__device__ __half g_Wqh[3*CDIM*CDIM];    // Wqkv in fp16
__device__ __half g_PWh[CDIM*CDIM];      // Wproj hi fp16
__device__ __half g_Qh[BB*NH*SEQ*HD];    // pre-scaled by QSC, fp16
__device__ __half g_Kh[BB*NH*SEQ*HD];    // fp16
__device__ __half g_Vth[BB*NH*HD*SEQ];   // fp16, TRANSPOSED per head: [b,h,d,n]
__device__ __half g_POh[M_TOT*CDIM];     // attention out hi fp16
__device__ __half g_POl[M_TOT*CDIM];     // attention out lo fp16

// ===========================================================================
// helpers
// ===========================================================================
__device__ __forceinline__ float ex2f(float x) {
    float y;
    asm("ex2.approx.ftz.f32 %0, %1;" : "=f"(y) : "f"(x));
    return y;
}
__device__ __forceinline__ uint32_t packh2(float lo, float hi) {  // {h0=lo, h1=hi}
    uint32_t d;
    asm("cvt.rn.f16x2.f32 %0, %1, %2;" : "=r"(d) : "f"(hi), "f"(lo));
    return d;
}
__device__ __forceinline__ void mma16(float* c,
                                      uint32_t a0, uint32_t a1, uint32_t a2, uint32_t a3,
                                      uint32_t b0, uint32_t b1) {
    asm volatile(
        "mma.sync.aligned.m16n8k16.row.col.f32.f16.f16.f32 "
        "{%0,%1,%2,%3}, {%4,%5,%6,%7}, {%8,%9}, {%0,%1,%2,%3};"
        : "+f"(c[0]), "+f"(c[1]), "+f"(c[2]), "+f"(c[3])
        : "r"(a0), "r"(a1), "r"(a2), "r"(a3), "r"(b0), "r"(b1));
}
__device__ __forceinline__ void ldsm_x4(uint32_t& r0, uint32_t& r1,
                                        uint32_t& r2, uint32_t& r3, uint32_t addr) {
    asm volatile("ldmatrix.sync.aligned.m8n8.x4.shared.b16 {%0,%1,%2,%3}, [%4];"
                 : "=r"(r0), "=r"(r1), "=r"(r2), "=r"(r3) : "r"(addr));
}
__device__ __forceinline__ uint32_t smem_u32(const void* p) {
    uint32_t a;
    asm("{ .reg .u64 t; cvta.to.shared.u64 t, %1; cvt.u32.u64 %0, t; }" : "=r"(a) : "l"(p));
    return a;
}
__device__ __forceinline__ void cpasync16(uint32_t dst, const void* src) {
    asm volatile("cp.async.cg.shared.global [%0], [%1], 16;" :: "r"(dst), "l"(src));
}
__device__ __forceinline__ void cp_commit() {
    asm volatile("cp.async.commit_group;" ::: "memory");
}
__device__ __forceinline__ void cp_wait0() {
    asm volatile("cp.async.wait_group 0;" ::: "memory");
}

// ===========================================================================
// Kernel 0: one-time fp32 -> fp16 conversion of X, Wqkv, Wproj(hi).
// ===========================================================================
#define NX4  (M_TOT*CDIM/4)
#define NWQ4 (3*CDIM*CDIM/4)
#define NWP4 (CDIM*CDIM/4)
#define CONV_BLOCKS ((NX4 + NWQ4 + NWP4 + 255)/256)

__global__ __launch_bounds__(256) void conv_in(const float* __restrict__ X,
                                               const float* __restrict__ Wq,
                                               const float* __restrict__ Wp) {
    int idx = blockIdx.x * 256 + threadIdx.x;
    if (idx < NX4) {
        float4 v = ((const float4*)X)[idx];
        ((__half2*)g_Xh)[idx*2    ] = __floats2half2_rn(v.x, v.y);
        ((__half2*)g_Xh)[idx*2 + 1] = __floats2half2_rn(v.z, v.w);
    } else if (idx < NX4 + NWQ4) {
        int j = idx - NX4;
        float4 v = ((const float4*)Wq)[j];
        ((__half2*)g_Wqh)[j*2    ] = __floats2half2_rn(v.x, v.y);
        ((__half2*)g_Wqh)[j*2 + 1] = __floats2half2_rn(v.z, v.w);
    } else if (idx < NX4 + NWQ4 + NWP4) {
        int j = idx - NX4 - NWQ4;
        float4 v = ((const float4*)Wp)[j];
        ((__half2*)g_PWh)[j*2    ] = __floats2half2_rn(v.x, v.y);
        ((__half2*)g_PWh)[j*2 + 1] = __floats2half2_rn(v.z, v.w);
    }
}

// ===========================================================================
// Kernel 1: QKV GEMM, pure-fp16 cp.async 2-stage (R14, unchanged).
// ===========================================================================
#define QP   72
#define QSTG (128*QP*2)
#define QKV_SMEM (4*QSTG)            // 73728
#define PT 130

__device__ __forceinline__ void qkv_prefetch(uint32_t sb, int st,
                                             const __half* Ab, const __half* Bb,
                                             int itk, int tid) {
#pragma unroll
    for (int i = 0; i < 4; i++) {
        int f = tid + i * 256;
        int row = f >> 3, c = f & 7;
        cpasync16(sb + st*QSTG + row*144 + c*16,
                  Ab + (size_t)row*CDIM + itk*64 + c*8);
        cpasync16(sb + 2*QSTG + st*QSTG + row*144 + c*16,
                  Bb + (size_t)row*CDIM + itk*64 + c*8);
    }
}

__global__ __launch_bounds__(256) void qkv_tc() {
    extern __shared__ char dsm[];
    const uint32_t sb = smem_u32(dsm);
    const int tid  = threadIdx.x;
    const int wid  = tid >> 5;
    const int lane = tid & 31;
    const int g    = lane >> 2;
    const int tig  = lane & 3;
    const int mw = wid >> 1, nw = wid & 1;
    const int m0 = blockIdx.y * 128;
    const int o0 = blockIdx.x * 128;
    const __half* Ab = g_Xh + (size_t)m0 * CDIM;
    const __half* Bb = g_Wqh + (size_t)o0 * CDIM;

    float acc[2][8][4];
#pragma unroll
    for (int mi = 0; mi < 2; mi++)
#pragma unroll
        for (int v = 0; v < 8; v++)
#pragma unroll
            for (int j = 0; j < 4; j++) acc[mi][v][j] = 0.f;

    qkv_prefetch(sb, 0, Ab, Bb, 0, tid);
    cp_commit();

    for (int it = 0; it < 12; it++) {
        cp_wait0();
        __syncthreads();
        if (it + 1 < 12) {
            qkv_prefetch(sb, (it + 1) & 1, Ab, Bb, it + 1, tid);
            cp_commit();
        }
        const __half* As = (const __half*)(dsm + (it & 1) * QSTG);
        const __half* Bs = (const __half*)(dsm + 2*QSTG + (it & 1) * QSTG);
#pragma unroll
        for (int ks = 0; ks < 4; ks++) {
            const int kc = ks*16 + 2*tig;
            uint32_t a[2][4];
#pragma unroll
            for (int mi = 0; mi < 2; mi++) {
                int row = mw*32 + mi*16 + g;
                a[mi][0] = *(const uint32_t*)&As[row      * QP + kc];
                a[mi][1] = *(const uint32_t*)&As[(row + 8)* QP + kc];
                a[mi][2] = *(const uint32_t*)&As[row      * QP + kc + 8];
                a[mi][3] = *(const uint32_t*)&As[(row + 8)* QP + kc + 8];
            }
#pragma unroll
            for (int v = 0; v < 8; v++) {
                int col = nw*64 + v*8 + g;
                uint32_t b0 = *(const uint32_t*)&Bs[col * QP + kc];
                uint32_t b1 = *(const uint32_t*)&Bs[col * QP + kc + 8];
                mma16(acc[0][v], a[0][0], a[0][1], a[0][2], a[0][3], b0, b1);
                mma16(acc[1][v], a[1][0], a[1][1], a[1][2], a[1][3], b0, b1);
            }
        }
    }
    __syncthreads();

    const int which = o0 / CDIM;
    const int oc0 = o0 - which * CDIM;
    const int bb = m0 >> 12;
    const int n0 = m0 & (SEQ - 1);

    if (which < 2) {
        __half* dstg = (which == 0) ? g_Qh : g_Kh;
        const float mul = (which == 0) ? QSC : 1.0f;
#pragma unroll
        for (int mi = 0; mi < 2; mi++) {
#pragma unroll
            for (int rr = 0; rr < 2; rr++) {
                int n = n0 + mw*32 + mi*16 + g + rr*8;
#pragma unroll
                for (int v = 0; v < 8; v++) {
                    int c = oc0 + nw*64 + v*8 + 2*tig;
                    int h = c / HD, d = c - h * HD;
                    __half2 hv = __floats2half2_rn(acc[mi][v][rr*2]     * mul,
                                                   acc[mi][v][rr*2 + 1] * mul);
                    *(__half2*)&dstg[((size_t)(bb*NH + h) * SEQ + n) * HD + d] = hv;
                }
            }
        }
    } else {
        __half* T = (__half*)dsm;
#pragma unroll
        for (int mi = 0; mi < 2; mi++) {
#pragma unroll
            for (int rr = 0; rr < 2; rr++) {
                int nl = mw*32 + mi*16 + g + rr*8;
#pragma unroll
                for (int v = 0; v < 8; v++) {
                    int cl = nw*64 + v*8 + 2*tig;
                    *(__half2*)&T[nl * PT + cl] =
                        __floats2half2_rn(acc[mi][v][rr*2], acc[mi][v][rr*2 + 1]);
                }
            }
        }
        __syncthreads();
        const size_t vrow0 = (size_t)(bb * NH * HD + oc0);
#pragma unroll
        for (int i = 0; i < 8; i++) {
            int f = tid + i * 256;
            int row = f >> 4;
            int ch  = f & 15;
            __half tmp[8];
#pragma unroll
            for (int j = 0; j < 8; j++) tmp[j] = T[(ch*8 + j) * PT + row];
            *(uint4*)&g_Vth[(vrow0 + row) * SEQ + n0 + ch*8] = *(uint4*)tmp;
        }
    }
}

// ===========================================================================
// Kernel 2: flash attention (R14 structure: q-tile 128, K+V double-buffered,
// one sync/kt) with ALL fragment loads via ldmatrix.x4 (4x fewer LDS issues).
// ===========================================================================
#define PQH 104
#define PKH 104
#define PVH 136
#define KSTG  26624
#define VSTG2 26112
#define SMK_OFF 26624
#define SMV_OFF (SMK_OFF + 2*KSTG)
#define ATTN_SMEM (SMV_OFF + 2*VSTG2)  // 132096

__device__ __forceinline__ void cp_tile_qk(uint32_t dst, const __half* src, int tid) {
#pragma unroll
    for (int i = 0; i < 6; i++) {
        int cf  = tid + i * 256;
        int row = cf / 12;
        int c   = cf - row * 12;
        cpasync16(dst + row * (PKH*2) + c * 16, src + (size_t)row * HD + c * 8);
    }
}
__device__ __forceinline__ void cp_tile_v(uint32_t dst, const __half* src, int tid) {
#pragma unroll
    for (int i = 0; i < 6; i++) {
        int cf  = tid + i * 256;
        int row = cf >> 4;
        int c   = cf & 15;
        cpasync16(dst + row * (PVH*2) + c * 16, src + (size_t)row * SEQ + c * 8);
    }
}

__global__ __launch_bounds__(256, 1) void attn_mma() {
    extern __shared__ char smc[];
    const uint32_t sb = smem_u32(smc);
    __shared__ float l_red[2][128];

    const int tid  = threadIdx.x;
    const int wid  = tid >> 5;
    const int lane = tid & 31;
    const int g    = lane >> 2;
    const int tig  = lane & 3;
    const int lane7 = lane & 7;
    const int tl    = lane >> 3;         // ldmatrix tile index 0..3
    const int mw = wid >> 1, nw = wid & 1;
    const int q0 = blockIdx.x * 128;
    const int bh = blockIdx.y;
    const int bbv = bh >> 3, hh = bh & 7;
    const size_t base  = (size_t)bh * SEQ * HD;
    const size_t vbase = (size_t)bh * HD * SEQ;

    cp_tile_qk(sb, &g_Qh[base + (size_t)q0 * HD], tid);
    cp_tile_qk(sb + SMK_OFF, &g_Kh[base], tid);
    cp_tile_v (sb + SMV_OFF, &g_Vth[vbase], tid);
    cp_commit();

    // ldmatrix per-lane bases:
    // Q A-frag (m16k16): tile0 rows m..m+7 @kc, tile1 rows+8 @kc, tile2 rows @kc+8, tile3 rows+8 @kc+8
    const uint32_t qa_base = sb +
        (uint32_t)(((mw*32 + (tl & 1)*8 + lane7) * PQH + (tl >> 1)*8) * 2);
    // K B-frag pair (n8k16 x2): tile0 rows n..n+7 @kc, tile1 same rows @kc+8,
    //                           tile2 rows n+8.. @kc, tile3 rows+8 @kc+8
    const uint32_t kb_base = sb + SMK_OFF +
        (uint32_t)(((nw*64 + (tl >> 1)*8 + lane7) * PKH + (tl & 1)*8) * 2);
    // V B-frag pair: rows = d (v*8..), cols = keys
    const uint32_t vb_off =
        (uint32_t)((((tl >> 1)*8 + lane7) * PVH + nw*64 + (tl & 1)*8) * 2);

    float oacc[2][12][4];
#pragma unroll
    for (int mi = 0; mi < 2; mi++)
#pragma unroll
        for (int v = 0; v < 12; v++)
#pragma unroll
            for (int j = 0; j < 4; j++) oacc[mi][v][j] = 0.f;
    float lsum[2][2] = {{0.f,0.f},{0.f,0.f}};

    for (int kt = 0; kt < SEQ / 128; kt++) {
        cp_wait0();
        __syncthreads();
        if (kt + 1 < SEQ / 128) {
            cp_tile_qk(sb + SMK_OFF + ((kt + 1) & 1) * KSTG,
                       &g_Kh[base + (size_t)(kt + 1) * 128 * HD], tid);
            cp_tile_v (sb + SMV_OFF + ((kt + 1) & 1) * VSTG2,
                       &g_Vth[vbase + (size_t)(kt + 1) * 128], tid);
            cp_commit();
        }
        const uint32_t kb = kb_base + (kt & 1) * KSTG;
        const uint32_t vb = sb + SMV_OFF + (kt & 1) * VSTG2 + vb_off;

        // ---- S = Q K^T ----
        float sacc[2][8][4];
#pragma unroll
        for (int mi = 0; mi < 2; mi++)
#pragma unroll
            for (int v = 0; v < 8; v++)
#pragma unroll
                for (int j = 0; j < 4; j++) sacc[mi][v][j] = 0.f;

#pragma unroll
        for (int t = 0; t < 6; t++) {
            uint32_t a[2][4];
            ldsm_x4(a[0][0], a[0][1], a[0][2], a[0][3], qa_base + (uint32_t)(t*32));
            ldsm_x4(a[1][0], a[1][1], a[1][2], a[1][3],
                    qa_base + (uint32_t)(16*PQH*2 + t*32));
#pragma unroll
            for (int v0 = 0; v0 < 8; v0 += 2) {
                uint32_t b0, b1, b2, b3;
                ldsm_x4(b0, b1, b2, b3, kb + (uint32_t)(v0*8*PKH*2 + t*32));
                mma16(sacc[0][v0],     a[0][0], a[0][1], a[0][2], a[0][3], b0, b1);
                mma16(sacc[1][v0],     a[1][0], a[1][1], a[1][2], a[1][3], b0, b1);
                mma16(sacc[0][v0 + 1], a[0][0], a[0][1], a[0][2], a[0][3], b2, b3);
                mma16(sacc[1][v0 + 1], a[1][0], a[1][1], a[1][2], a[1][3], b2, b3);
            }
        }

        // ---- fused softmax + PV ----
#pragma unroll
        for (int ks = 0; ks < 4; ks++) {
            uint32_t pa[2][4];
#pragma unroll
            for (int mi = 0; mi < 2; mi++) {
                float* u0 = sacc[mi][2*ks];
                float* u1 = sacc[mi][2*ks + 1];
                float e0 = ex2f(u0[0]), e1 = ex2f(u0[1]);
                float e2 = ex2f(u0[2]), e3 = ex2f(u0[3]);
                float f0 = ex2f(u1[0]), f1 = ex2f(u1[1]);
                float f2 = ex2f(u1[2]), f3 = ex2f(u1[3]);
                lsum[mi][0] += (e0 + e1) + (f0 + f1);
                lsum[mi][1] += (e2 + e3) + (f2 + f3);
                pa[mi][0] = packh2(e0, e1);
                pa[mi][1] = packh2(e2, e3);
                pa[mi][2] = packh2(f0, f1);
                pa[mi][3] = packh2(f2, f3);
            }
#pragma unroll
            for (int v0 = 0; v0 < 12; v0 += 2) {
                uint32_t b0, b1, b2, b3;
                ldsm_x4(b0, b1, b2, b3, vb + (uint32_t)(v0*8*PVH*2 + ks*32));
                mma16(oacc[0][v0],     pa[0][0], pa[0][1], pa[0][2], pa[0][3], b0, b1);
                mma16(oacc[1][v0],     pa[1][0], pa[1][1], pa[1][2], pa[1][3], b0, b1);
                mma16(oacc[0][v0 + 1], pa[0][0], pa[0][1], pa[0][2], pa[0][3], b2, b3);
                mma16(oacc[1][v0 + 1], pa[1][0], pa[1][1], pa[1][2], pa[1][3], b2, b3);
            }
        }
    }

    // ---- epilogue: cross-nw reduction, hi/lo fp16 emission ----
    __syncthreads();
#pragma unroll
    for (int mi = 0; mi < 2; mi++)
#pragma unroll
        for (int h = 0; h < 2; h++) {
            float l = lsum[mi][h];
            l += __shfl_xor_sync(0xffffffffu, l, 1);
            l += __shfl_xor_sync(0xffffffffu, l, 2);
            lsum[mi][h] = l;
        }
    if (tig == 0) {
#pragma unroll
        for (int mi = 0; mi < 2; mi++)
#pragma unroll
            for (int h = 0; h < 2; h++)
                l_red[nw][mw*32 + mi*16 + g + h*8] = lsum[mi][h];
    }
    float* red = (float*)smc;
    if (nw == 1) {
#pragma unroll
        for (int mi = 0; mi < 2; mi++)
#pragma unroll
            for (int h = 0; h < 2; h++) {
                int row = mw*32 + mi*16 + g + h*8;
#pragma unroll
                for (int v = 0; v < 12; v++)
                    *(float2*)&red[row * 100 + v*8 + 2*tig] =
                        make_float2(oacc[mi][v][2*h], oacc[mi][v][2*h + 1]);
            }
    }
    __syncthreads();
    if (nw == 0) {
#pragma unroll
        for (int mi = 0; mi < 2; mi++)
#pragma unroll
            for (int h = 0; h < 2; h++) {
                int row = mw*32 + mi*16 + g + h*8;
                float inv = 1.f / (l_red[0][row] + l_red[1][row]);
                int n = q0 + row;
                size_t ob = ((size_t)bbv * SEQ + n) * CDIM + hh * HD;
#pragma unroll
                for (int v = 0; v < 12; v++) {
                    float2 p = *(float2*)&red[row * 100 + v*8 + 2*tig];
                    float v0 = (oacc[mi][v][2*h]     + p.x) * inv;
                    float v1 = (oacc[mi][v][2*h + 1] + p.y) * inv;
                    __half h0 = __float2half_rn(v0);
                    __half h1 = __float2half_rn(v1);
                    __half l0 = __float2half_rn(v0 - __half2float(h0));
                    __half l1 = __float2half_rn(v1 - __half2float(h1));
                    size_t off = ob + v*8 + 2*tig;
                    *(__half2*)&g_POh[off] = __halves2half2(h0, h1);
                    *(__half2*)&g_POl[off] = __halves2half2(l0, l1);
                }
            }
    }
}

// ===========================================================================
// Kernel 3: output projection, 2-term compensated fp16 (R14, unchanged).
// ===========================================================================
#define PP   40
#define PSTG (128*PP*2)
#define PROJ_SMEM (6*PSTG)             // 61440

__device__ __forceinline__ void proj_prefetch(uint32_t sb, int st,
                                              const __half* AhG, const __half* AlG,
                                              const __half* BhG, int itk, int tid) {
#pragma unroll
    for (int i = 0; i < 2; i++) {
        int f = tid + i * 256;
        int row = f >> 2, c = f & 3;
        cpasync16(sb + st*PSTG + row*80 + c*16,
                  AhG + (size_t)row*CDIM + itk*32 + c*8);
        cpasync16(sb + 2*PSTG + st*PSTG + row*80 + c*16,
                  AlG + (size_t)row*CDIM + itk*32 + c*8);
        cpasync16(sb + 4*PSTG + st*PSTG + row*80 + c*16,
                  BhG + (size_t)row*CDIM + itk*32 + c*8);
    }
}

__global__ __launch_bounds__(256) void proj_tc(float* __restrict__ out) {
    extern __shared__ char dsm[];
    const uint32_t sb = smem_u32(dsm);
    const int tid  = threadIdx.x;
    const int wid  = tid >> 5;
    const int lane = tid & 31;
    const int g    = lane >> 2;
    const int tig  = lane & 3;
    const int mw = wid >> 1, nw = wid & 1;
    const int m0 = blockIdx.y * 128;
    const int o0 = blockIdx.x * 128;
    const __half* AhG = g_POh + (size_t)m0 * CDIM;
    const __half* AlG = g_POl + (size_t)m0 * CDIM;
    const __half* BhG = g_PWh + (size_t)o0 * CDIM;

    float acc[2][8][4];
#pragma unroll
    for (int mi = 0; mi < 2; mi++)
#pragma unroll
        for (int v = 0; v < 8; v++)
#pragma unroll
            for (int j = 0; j < 4; j++) acc[mi][v][j] = 0.f;

    proj_prefetch(sb, 0, AhG, AlG, BhG, 0, tid);
    cp_commit();

    for (int it = 0; it < 24; it++) {
        cp_wait0();
        __syncthreads();
        if (it + 1 < 24) {
            proj_prefetch(sb, (it + 1) & 1, AhG, AlG, BhG, it + 1, tid);
            cp_commit();
        }
        const __half* Ah = (const __half*)(dsm + (it & 1) * PSTG);
        const __half* Al = (const __half*)(dsm + 2*PSTG + (it & 1) * PSTG);
        const __half* Bh = (const __half*)(dsm + 4*PSTG + (it & 1) * PSTG);
#pragma unroll
        for (int ks = 0; ks < 2; ks++) {
            const int kc = ks*16 + 2*tig;
            uint32_t ah[2][4], al[2][4];
#pragma unroll
            for (int mi = 0; mi < 2; mi++) {
                int row = mw*32 + mi*16 + g;
                ah[mi][0] = *(const uint32_t*)&Ah[row      * PP + kc];
                ah[mi][1] = *(const uint32_t*)&Ah[(row + 8)* PP + kc];
                ah[mi][2] = *(const uint32_t*)&Ah[row      * PP + kc + 8];
                ah[mi][3] = *(const uint32_t*)&Ah[(row + 8)* PP + kc + 8];
                al[mi][0] = *(const uint32_t*)&Al[row      * PP + kc];
                al[mi][1] = *(const uint32_t*)&Al[(row + 8)* PP + kc];
                al[mi][2] = *(const uint32_t*)&Al[row      * PP + kc + 8];
                al[mi][3] = *(const uint32_t*)&Al[(row + 8)* PP + kc + 8];
            }
#pragma unroll
            for (int v = 0; v < 8; v++) {
                int col = nw*64 + v*8 + g;
                uint32_t b0 = *(const uint32_t*)&Bh[col * PP + kc];
                uint32_t b1 = *(const uint32_t*)&Bh[col * PP + kc + 8];
#pragma unroll
                for (int mi = 0; mi < 2; mi++) {
                    mma16(acc[mi][v], al[mi][0], al[mi][1], al[mi][2], al[mi][3], b0, b1);
                    mma16(acc[mi][v], ah[mi][0], ah[mi][1], ah[mi][2], ah[mi][3], b0, b1);
                }
            }
        }
    }

#pragma unroll
    for (int mi = 0; mi < 2; mi++) {
#pragma unroll
        for (int rr = 0; rr < 2; rr++) {
            int m = m0 + mw*32 + mi*16 + g + rr*8;
#pragma unroll
            for (int v = 0; v < 8; v++) {
                int o = o0 + nw*64 + v*8 + 2*tig;
                *(float2*)&out[(size_t)m * CDIM + o] =
                    make_float2(acc[mi][v][rr*2], acc[mi][v][rr*2 + 1]);
            }
        }
    }
}

// ===========================================================================
extern "C" void kernel_launch(void* const* d_in, const int* in_sizes, int n_in,
                              void* d_out, int out_size) {
    const float *x = nullptr, *w_qkv = nullptr, *w_proj = nullptr;
    for (int i = 0; i < n_in; i++) {
        if (in_sizes[i] == BB * SEQ * CDIM)       x      = (const float*)d_in[i];
        else if (in_sizes[i] == 3 * CDIM * CDIM)  w_qkv  = (const float*)d_in[i];
        else if (in_sizes[i] == CDIM * CDIM)      w_proj = (const float*)d_in[i];
    }
    float* out = (float*)d_out;

    conv_in<<<CONV_BLOCKS, 256>>>(x, w_qkv, w_proj);

    cudaFuncSetAttribute(qkv_tc, cudaFuncAttributeMaxDynamicSharedMemorySize, QKV_SMEM);
    qkv_tc<<<dim3(3*CDIM/128, M_TOT/128), 256, QKV_SMEM>>>();

    cudaFuncSetAttribute(attn_mma, cudaFuncAttributeMaxDynamicSharedMemorySize, ATTN_SMEM);
    attn_mma<<<dim3(SEQ/128, BB*NH), 256, ATTN_SMEM>>>();

    cudaFuncSetAttribute(proj_tc, cudaFuncAttributeMaxDynamicSharedMemorySize, PROJ_SMEM);
    proj_tc<<<dim3(CDIM/128, M_TOT/128), 256, PROJ_SMEM>>>(out);
}